// round 5
// baseline (speedup 1.0000x reference)
#include <cuda_runtime.h>
#include <cstddef>

#define N_DIM 4096
#define B_DIM 2048
#define RANK  4
#define INV_N (1.0f / 4096.0f)

// erf(alpha*x) ~= tanh( x * (1 + x^2*(C3P + C5P*x^2)) )   [alpha folded: c1'=1]
#define ERF_C3P 0.0721781f
#define ERF_C5P (-0.000887f)

#define ROWS 16
#define THREADS 256
#define GRID_X 2                       // column halves (256 thr * 4 cols)
#define GRID_Y (N_DIM / ROWS)          // 256 row groups
#define NBLOCKS (GRID_X * GRID_Y)      // 512

// Scratch: rows 0..3 = s[r][B], row 4 = y_acc[B], then barrier counter.
// All zeroed by one memsetAsync per launch.
__device__ __align__(16) float g_acc[5 * B_DIM + 4];

typedef unsigned long long u64;

__device__ __forceinline__ u64 pack2(float lo, float hi) {
    u64 r; asm("mov.b64 %0, {%1,%2};" : "=l"(r) : "f"(lo), "f"(hi)); return r;
}
__device__ __forceinline__ void unpack2(u64 v, float& lo, float& hi) {
    asm("mov.b64 {%0,%1}, %2;" : "=f"(lo), "=f"(hi) : "l"(v));
}
__device__ __forceinline__ u64 fma2(u64 a, u64 b, u64 c) {
    u64 d; asm("fma.rn.f32x2 %0, %1, %2, %3;" : "=l"(d) : "l"(a), "l"(b), "l"(c)); return d;
}
__device__ __forceinline__ u64 mul2(u64 a, u64 b) {
    u64 d; asm("mul.rn.f32x2 %0, %1, %2;" : "=l"(d) : "l"(a), "l"(b)); return d;
}
__device__ __forceinline__ float tanh_fast(float x) {
    float y; asm("tanh.approx.f32 %0, %1;" : "=f"(y) : "f"(x)); return y;
}

__device__ __forceinline__ u64 phi2(u64 X, u64 C3, u64 C5, u64 ONE) {
    u64 S = mul2(X, X);
    u64 K = fma2(C5, S, C3);
    K = fma2(K, S, ONE);
    u64 A = mul2(K, X);
    float a0, a1; unpack2(A, a0, a1);
    return pack2(tanh_fast(a0), tanh_fast(a1));
}

// ---------------------------------------------------------------------------
// Fused kernel.
// Phase 1 (reduce): block (bx,by) covers rows [by*16, by*16+16) x 1024 cols,
//   accumulates s[j] and y into g_acc via red.global.add.v4.
// Grid barrier (arrive counter in g_acc tail, pre-zeroed by memset).
// Phase 2 (finalize): same block writes h_new for its 16 rows x 1024 cols:
//   h_new[n][b] = m[n]*x_t[b] + (sum_j u[n][j]*s[j][b])/N. by==0 blocks emit y.
// __launch_bounds__(256,4): 4 CTAs/SM * 148 SMs = 592 >= 512 -> all resident,
// grid barrier cannot deadlock.
// ---------------------------------------------------------------------------
__global__ void __launch_bounds__(THREADS, 4)
fused_kernel(const float* __restrict__ h,
             const float* __restrict__ v,
             const float* __restrict__ z,
             const float* __restrict__ x_t,
             const float* __restrict__ u,
             const float* __restrict__ m,
             float* __restrict__ out) {
    __shared__ u64    svz[ROWS][5];
    __shared__ float4 s_u[ROWS];
    __shared__ float  s_m[ROWS];

    const int tid = threadIdx.x;
    const int bx  = blockIdx.x;     // 0..1
    const int by  = blockIdx.y;     // 0..255
    const int n0  = by * ROWS;

    // stage v/z for reduce AND u/m for finalize (DISJOINT thread ranges)
    if (tid < ROWS * 5) {                     // tid in [0, 80)
        int r = tid / 5, j = tid % 5;
        float val = (j < 4) ? v[(size_t)(n0 + r) * RANK + j] : z[n0 + r];
        svz[r][j] = pack2(val, val);
    }
    if (tid >= 128 && tid < 128 + ROWS) {     // tid in [128, 144)
        int r = tid - 128;
        s_u[r] = reinterpret_cast<const float4*>(u)[n0 + r];
        s_m[r] = m[n0 + r];
    }
    __syncthreads();

    const u64 C3  = pack2(ERF_C3P, ERF_C3P);
    const u64 C5  = pack2(ERF_C5P, ERF_C5P);
    const u64 ONE = pack2(1.0f, 1.0f);

    const int q  = bx * THREADS + tid;      // column quad index [0,512)
    const int b0 = q * 4;
    const int BQ = B_DIM / 4;

    // ---------------- Phase 1: reduce ----------------
    u64 acc0[5], acc1[5];
    #pragma unroll
    for (int j = 0; j < 5; j++) { acc0[j] = 0ull; acc1[j] = 0ull; }

    #pragma unroll
    for (int rb = 0; rb < ROWS; rb += 8) {
        float4 hv[8];
        #pragma unroll
        for (int i = 0; i < 8; i++)
            hv[i] = *reinterpret_cast<const float4*>(h + (size_t)(n0 + rb + i) * B_DIM + b0);
        #pragma unroll
        for (int i = 0; i < 8; i++) {
            const int r = rb + i;
            u64 P0 = phi2(pack2(hv[i].x, hv[i].y), C3, C5, ONE);
            u64 P1 = phi2(pack2(hv[i].z, hv[i].w), C3, C5, ONE);
            #pragma unroll
            for (int j = 0; j < 5; j++) {
                u64 w = svz[r][j];
                acc0[j] = fma2(w, P0, acc0[j]);
                acc1[j] = fma2(w, P1, acc1[j]);
            }
        }
    }

    #pragma unroll
    for (int j = 0; j < 5; j++) {
        float a0, a1, a2, a3;
        unpack2(acc0[j], a0, a1);
        unpack2(acc1[j], a2, a3);
        float* p = g_acc + j * B_DIM + b0;
        asm volatile("red.global.add.v4.f32 [%0], {%1,%2,%3,%4};"
                     :: "l"(p), "f"(a0), "f"(a1), "f"(a2), "f"(a3) : "memory");
    }

    // ---------------- Grid barrier ----------------
    {
        unsigned int* bar = reinterpret_cast<unsigned int*>(g_acc + 5 * B_DIM);
        __threadfence();               // make reds visible before arrive
        __syncthreads();
        if (tid == 0) {
            asm volatile("red.release.gpu.global.add.u32 [%0], 1;" :: "l"(bar) : "memory");
            unsigned int cnt;
            do {
                asm volatile("ld.acquire.gpu.global.u32 %0, [%1];"
                             : "=r"(cnt) : "l"(bar) : "memory");
            } while (cnt < (unsigned int)NBLOCKS);
        }
        __syncthreads();
    }

    // ---------------- Phase 2: finalize ----------------
    float4 a = reinterpret_cast<const float4*>(g_acc)[0 * BQ + q];
    float4 b = reinterpret_cast<const float4*>(g_acc)[1 * BQ + q];
    float4 c = reinterpret_cast<const float4*>(g_acc)[2 * BQ + q];
    float4 d = reinterpret_cast<const float4*>(g_acc)[3 * BQ + q];
    a.x *= INV_N; a.y *= INV_N; a.z *= INV_N; a.w *= INV_N;
    b.x *= INV_N; b.y *= INV_N; b.z *= INV_N; b.w *= INV_N;
    c.x *= INV_N; c.y *= INV_N; c.z *= INV_N; c.w *= INV_N;
    d.x *= INV_N; d.y *= INV_N; d.z *= INV_N; d.w *= INV_N;
    const float4 xt = reinterpret_cast<const float4*>(x_t)[q];

    float4* op = reinterpret_cast<float4*>(out + B_DIM) + (size_t)n0 * BQ + q;

    #pragma unroll
    for (int r = 0; r < ROWS; r++) {
        const float4 uv = s_u[r];
        const float  mm = s_m[r];
        float4 o;
        o.x = fmaf(uv.x, a.x, fmaf(uv.y, b.x, fmaf(uv.z, c.x, fmaf(uv.w, d.x, mm * xt.x))));
        o.y = fmaf(uv.x, a.y, fmaf(uv.y, b.y, fmaf(uv.z, c.y, fmaf(uv.w, d.y, mm * xt.y))));
        o.z = fmaf(uv.x, a.z, fmaf(uv.y, b.z, fmaf(uv.z, c.z, fmaf(uv.w, d.z, mm * xt.z))));
        o.w = fmaf(uv.x, a.w, fmaf(uv.y, b.w, fmaf(uv.z, c.w, fmaf(uv.w, d.w, mm * xt.w))));
        *op = o;
        op += BQ;
    }

    if (by == 0) {   // 2 blocks emit y = y_acc / N
        float4 yv = reinterpret_cast<const float4*>(g_acc)[4 * BQ + q];
        yv.x *= INV_N; yv.y *= INV_N; yv.z *= INV_N; yv.w *= INV_N;
        reinterpret_cast<float4*>(out)[q] = yv;
    }
}

// ---------------------------------------------------------------------------
// Launch. Inputs: x_t[B], h[N*B], m[N], u[N*4], v[N*4], z[N].
// Output: [ y (B) | h_new (N*B) ] float32.
// ---------------------------------------------------------------------------
extern "C" void kernel_launch(void* const* d_in, const int* in_sizes, int n_in,
                              void* d_out, int out_size) {
    const float* x_t = (const float*)d_in[0];
    const float* h   = (const float*)d_in[1];
    const float* m   = (const float*)d_in[2];
    const float* u   = (const float*)d_in[3];
    const float* v   = (const float*)d_in[4];
    const float* z   = (const float*)d_in[5];
    float* out = (float*)d_out;
    (void)in_sizes; (void)n_in; (void)out_size;

    void* acc_ptr = nullptr;
    cudaGetSymbolAddress(&acc_ptr, g_acc);
    cudaMemsetAsync(acc_ptr, 0, (5 * B_DIM + 4) * sizeof(float));

    dim3 grid(GRID_X, GRID_Y);   // (2, 256) = 512 blocks
    fused_kernel<<<grid, THREADS>>>(h, v, z, x_t, u, m, out);
}

// round 6
// speedup vs baseline: 1.1011x; 1.1011x over previous
#include <cuda_runtime.h>
#include <cstddef>

#define N_DIM 4096
#define B_DIM 2048
#define RANK  4
#define INV_N (1.0f / 4096.0f)

// erf(alpha*x) ~= tanh( x * (1 + x^2*(C3P + C5P*x^2)) )   [alpha folded: c1'=1]
#define ERF_C3P 0.0721781f
#define ERF_C5P (-0.000887f)

// Scratch: rows 0..3 = s[r][B] (pre-scaled by 1/N), row 4 = y[B] (pre-scaled)
__device__ __align__(16) float g_acc[5 * B_DIM];

typedef unsigned long long u64;

__device__ __forceinline__ u64 pack2(float lo, float hi) {
    u64 r; asm("mov.b64 %0, {%1,%2};" : "=l"(r) : "f"(lo), "f"(hi)); return r;
}
__device__ __forceinline__ void unpack2(u64 v, float& lo, float& hi) {
    asm("mov.b64 {%0,%1}, %2;" : "=f"(lo), "=f"(hi) : "l"(v));
}
__device__ __forceinline__ u64 fma2(u64 a, u64 b, u64 c) {
    u64 d; asm("fma.rn.f32x2 %0, %1, %2, %3;" : "=l"(d) : "l"(a), "l"(b), "l"(c)); return d;
}
__device__ __forceinline__ u64 add2(u64 a, u64 b) {
    u64 d; asm("add.rn.f32x2 %0, %1, %2;" : "=l"(d) : "l"(a), "l"(b)); return d;
}
__device__ __forceinline__ u64 mul2(u64 a, u64 b) {
    u64 d; asm("mul.rn.f32x2 %0, %1, %2;" : "=l"(d) : "l"(a), "l"(b)); return d;
}
__device__ __forceinline__ float tanh_fast(float x) {
    float y; asm("tanh.approx.f32 %0, %1;" : "=f"(y) : "f"(x)); return y;
}

__device__ __forceinline__ u64 phi2(u64 X, u64 C3, u64 C5, u64 ONE) {
    u64 S = mul2(X, X);
    u64 K = fma2(C5, S, C3);
    K = fma2(K, S, ONE);
    u64 A = mul2(K, X);
    float a0, a1; unpack2(A, a0, a1);
    return pack2(tanh_fast(a0), tanh_fast(a1));
}

// ---------------------------------------------------------------------------
// Reduce: s[j][b] += sum_n (v[n][j]/N) * phi(h[n][b]);  same for y with z/N.
// Block = 4 row-subgroups (ty) x 64 column-quads (tx). Each thread does 8 rows.
// Block covers 32 rows x 256 cols. Grid (8, 128) = 1024 blocks.
// Intra-block SMEM reduction over ty before one red.global.add.v4 per (tx,j).
// ---------------------------------------------------------------------------
#define BLK_ROWS 32
#define R_PER_T  8
#define QUADS_PB 64

__global__ void reduce_kernel(const float* __restrict__ h,
                              const float* __restrict__ v,
                              const float* __restrict__ z) {
    __shared__ u64 svz[BLK_ROWS][5];          // weights (pre-scaled by 1/N)
    __shared__ u64 s_red[3][QUADS_PB][5][2];  // partials from ty=1..3 (15 KB)

    const int tid = threadIdx.x;
    const int ty  = tid >> 6;       // 0..3 row subgroup
    const int tx  = tid & 63;       // 0..63 quad within block
    const int n0b = blockIdx.y * BLK_ROWS;

    if (tid < BLK_ROWS * 5) {
        int r = tid / 5, j = tid % 5;
        float val = ((j < 4) ? v[(size_t)(n0b + r) * RANK + j] : z[n0b + r]) * INV_N;
        svz[r][j] = pack2(val, val);
    }
    __syncthreads();

    const u64 C3  = pack2(ERF_C3P, ERF_C3P);
    const u64 C5  = pack2(ERF_C5P, ERF_C5P);
    const u64 ONE = pack2(1.0f, 1.0f);

    const int q  = blockIdx.x * QUADS_PB + tx;   // quad index [0,512)
    const int b0 = q * 4;
    const int n0 = n0b + ty * R_PER_T;

    u64 acc0[5], acc1[5];
    #pragma unroll
    for (int j = 0; j < 5; j++) { acc0[j] = 0ull; acc1[j] = 0ull; }

    #pragma unroll
    for (int rb = 0; rb < R_PER_T; rb += 4) {
        float4 hv[4];
        #pragma unroll
        for (int i = 0; i < 4; i++)
            hv[i] = *reinterpret_cast<const float4*>(h + (size_t)(n0 + rb + i) * B_DIM + b0);
        #pragma unroll
        for (int i = 0; i < 4; i++) {
            const int r = ty * R_PER_T + rb + i;
            u64 P0 = phi2(pack2(hv[i].x, hv[i].y), C3, C5, ONE);
            u64 P1 = phi2(pack2(hv[i].z, hv[i].w), C3, C5, ONE);
            #pragma unroll
            for (int j = 0; j < 5; j++) {
                u64 w = svz[r][j];
                acc0[j] = fma2(w, P0, acc0[j]);
                acc1[j] = fma2(w, P1, acc1[j]);
            }
        }
    }

    // intra-block reduce over ty (4 -> 1), then one global red per (tx, j)
    if (ty > 0) {
        #pragma unroll
        for (int j = 0; j < 5; j++) {
            s_red[ty - 1][tx][j][0] = acc0[j];
            s_red[ty - 1][tx][j][1] = acc1[j];
        }
    }
    __syncthreads();
    if (ty == 0) {
        #pragma unroll
        for (int j = 0; j < 5; j++) {
            u64 a = acc0[j], b = acc1[j];
            #pragma unroll
            for (int t = 0; t < 3; t++) {
                a = add2(a, s_red[t][tx][j][0]);
                b = add2(b, s_red[t][tx][j][1]);
            }
            float a0, a1, a2, a3;
            unpack2(a, a0, a1);
            unpack2(b, a2, a3);
            float* p = g_acc + j * B_DIM + b0;
            asm volatile("red.global.add.v4.f32 [%0], {%1,%2,%3,%4};"
                         :: "l"(p), "f"(a0), "f"(a1), "f"(a2), "f"(a3) : "memory");
        }
    }
}

// ---------------------------------------------------------------------------
// Finalize: h_new[n][b] = m[n]*x_t[b] + sum_j u[n][j]*s[j][b]   (s pre-scaled)
//           y[b] = g_acc[4][b]                                  (pre-scaled)
// Thread owns a column-quad; 8 rows per block; grid (2, 512) = 1024 blocks.
// ---------------------------------------------------------------------------
#define FROWS 8
#define FIN_THREADS 256

__global__ void finalize_kernel(const float* __restrict__ x_t,
                                const float* __restrict__ u,
                                const float* __restrict__ m,
                                float* __restrict__ out) {
    __shared__ float4 s_u[FROWS];
    __shared__ float  s_m[FROWS];

    const int tid = threadIdx.x;
    const int n0  = blockIdx.y * FROWS;

    if (tid < FROWS) {
        s_u[tid] = reinterpret_cast<const float4*>(u)[n0 + tid];
        s_m[tid] = m[n0 + tid];
    }

    const int q  = blockIdx.x * FIN_THREADS + tid;   // [0,512)
    const int BQ = B_DIM / 4;

    const float4 a  = reinterpret_cast<const float4*>(g_acc)[0 * BQ + q];
    const float4 b  = reinterpret_cast<const float4*>(g_acc)[1 * BQ + q];
    const float4 c  = reinterpret_cast<const float4*>(g_acc)[2 * BQ + q];
    const float4 d  = reinterpret_cast<const float4*>(g_acc)[3 * BQ + q];
    const float4 xt = reinterpret_cast<const float4*>(x_t)[q];

    __syncthreads();

    float4* op = reinterpret_cast<float4*>(out + B_DIM) + (size_t)n0 * BQ + q;

    #pragma unroll
    for (int r = 0; r < FROWS; r++) {
        const float4 uv = s_u[r];
        const float  mm = s_m[r];
        float4 o;
        o.x = fmaf(uv.x, a.x, fmaf(uv.y, b.x, fmaf(uv.z, c.x, fmaf(uv.w, d.x, mm * xt.x))));
        o.y = fmaf(uv.x, a.y, fmaf(uv.y, b.y, fmaf(uv.z, c.y, fmaf(uv.w, d.y, mm * xt.y))));
        o.z = fmaf(uv.x, a.z, fmaf(uv.y, b.z, fmaf(uv.z, c.z, fmaf(uv.w, d.z, mm * xt.z))));
        o.w = fmaf(uv.x, a.w, fmaf(uv.y, b.w, fmaf(uv.z, c.w, fmaf(uv.w, d.w, mm * xt.w))));
        *op = o;
        op += BQ;
    }

    if (blockIdx.y == 0) {   // emit y (already scaled)
        reinterpret_cast<float4*>(out)[q] =
            reinterpret_cast<const float4*>(g_acc)[4 * BQ + q];
    }
}

// ---------------------------------------------------------------------------
// Launch. Inputs: x_t[B], h[N*B], m[N], u[N*4], v[N*4], z[N].
// Output: [ y (B) | h_new (N*B) ] float32.
// ---------------------------------------------------------------------------
extern "C" void kernel_launch(void* const* d_in, const int* in_sizes, int n_in,
                              void* d_out, int out_size) {
    const float* x_t = (const float*)d_in[0];
    const float* h   = (const float*)d_in[1];
    const float* m   = (const float*)d_in[2];
    const float* u   = (const float*)d_in[3];
    const float* v   = (const float*)d_in[4];
    const float* z   = (const float*)d_in[5];
    float* out = (float*)d_out;
    (void)in_sizes; (void)n_in; (void)out_size;

    void* acc_ptr = nullptr;
    cudaGetSymbolAddress(&acc_ptr, g_acc);
    cudaMemsetAsync(acc_ptr, 0, 5 * B_DIM * sizeof(float));

    dim3 rgrid(B_DIM / (QUADS_PB * 4), N_DIM / BLK_ROWS);   // (8, 128) = 1024
    reduce_kernel<<<rgrid, 256>>>(h, v, z);

    dim3 fgrid(2, N_DIM / FROWS);                            // (2, 512) = 1024
    finalize_kernel<<<fgrid, FIN_THREADS>>>(x_t, u, m, out);
}

// round 7
// speedup vs baseline: 1.1366x; 1.0323x over previous
#include <cuda_runtime.h>
#include <cstddef>

#define N_DIM 4096
#define B_DIM 2048
#define RANK  4
#define INV_N (1.0f / 4096.0f)

// erf(alpha*x) ~= tanh( x * (1 + x^2*(C3P + C5P*x^2)) )   [alpha folded: c1'=1]
#define ERF_C3P 0.0721781f
#define ERF_C5P (-0.000887f)

// Scratch: rows 0..3 = s[r][B] (pre-scaled by 1/N), row 4 = y[B] (pre-scaled)
__device__ __align__(16) float g_acc[5 * B_DIM];

typedef unsigned long long u64;

__device__ __forceinline__ u64 pack2(float lo, float hi) {
    u64 r; asm("mov.b64 %0, {%1,%2};" : "=l"(r) : "f"(lo), "f"(hi)); return r;
}
__device__ __forceinline__ void unpack2(u64 v, float& lo, float& hi) {
    asm("mov.b64 {%0,%1}, %2;" : "=f"(lo), "=f"(hi) : "l"(v));
}
__device__ __forceinline__ u64 fma2(u64 a, u64 b, u64 c) {
    u64 d; asm("fma.rn.f32x2 %0, %1, %2, %3;" : "=l"(d) : "l"(a), "l"(b), "l"(c)); return d;
}
__device__ __forceinline__ u64 add2(u64 a, u64 b) {
    u64 d; asm("add.rn.f32x2 %0, %1, %2;" : "=l"(d) : "l"(a), "l"(b)); return d;
}
__device__ __forceinline__ u64 mul2(u64 a, u64 b) {
    u64 d; asm("mul.rn.f32x2 %0, %1, %2;" : "=l"(d) : "l"(a), "l"(b)); return d;
}
__device__ __forceinline__ float tanh_fast(float x) {
    float y; asm("tanh.approx.f32 %0, %1;" : "=f"(y) : "f"(x)); return y;
}

__device__ __forceinline__ u64 phi2(u64 X, u64 C3, u64 C5, u64 ONE) {
    u64 S = mul2(X, X);
    u64 K = fma2(C5, S, C3);
    K = fma2(K, S, ONE);
    u64 A = mul2(K, X);
    float a0, a1; unpack2(A, a0, a1);
    return pack2(tanh_fast(a0), tanh_fast(a1));
}

// ---------------------------------------------------------------------------
// Reduce: s[j][b] += sum_n (v[n][j]/N) * phi(h[n][b]);  same for y with z/N.
// Block = 4 row-subgroups (ty) x 64 column-quads (tx). Each thread does 8 rows.
// Block covers 32 rows x 256 cols. Grid (8, 128) = 1024 blocks.
// Intra-block SMEM reduction over ty before one red.global.add.v4 per (tx,j).
// ---------------------------------------------------------------------------
#define BLK_ROWS 32
#define R_PER_T  8
#define QUADS_PB 64

__global__ void reduce_kernel(const float* __restrict__ h,
                              const float* __restrict__ v,
                              const float* __restrict__ z) {
    __shared__ u64 svz[BLK_ROWS][5];          // weights (pre-scaled by 1/N)
    __shared__ u64 s_red[3][QUADS_PB][5][2];  // partials from ty=1..3 (15 KB)

    const int tid = threadIdx.x;
    const int ty  = tid >> 6;       // 0..3 row subgroup
    const int tx  = tid & 63;       // 0..63 quad within block
    const int n0b = blockIdx.y * BLK_ROWS;

    if (tid < BLK_ROWS * 5) {
        int r = tid / 5, j = tid % 5;
        float val = ((j < 4) ? v[(size_t)(n0b + r) * RANK + j] : z[n0b + r]) * INV_N;
        svz[r][j] = pack2(val, val);
    }
    __syncthreads();

    const u64 C3  = pack2(ERF_C3P, ERF_C3P);
    const u64 C5  = pack2(ERF_C5P, ERF_C5P);
    const u64 ONE = pack2(1.0f, 1.0f);

    const int q  = blockIdx.x * QUADS_PB + tx;   // quad index [0,512)
    const int b0 = q * 4;
    const int n0 = n0b + ty * R_PER_T;

    u64 acc0[5], acc1[5];
    #pragma unroll
    for (int j = 0; j < 5; j++) { acc0[j] = 0ull; acc1[j] = 0ull; }

    #pragma unroll
    for (int rb = 0; rb < R_PER_T; rb += 4) {
        float4 hv[4];
        #pragma unroll
        for (int i = 0; i < 4; i++)
            hv[i] = *reinterpret_cast<const float4*>(h + (size_t)(n0 + rb + i) * B_DIM + b0);
        #pragma unroll
        for (int i = 0; i < 4; i++) {
            const int r = ty * R_PER_T + rb + i;
            u64 P0 = phi2(pack2(hv[i].x, hv[i].y), C3, C5, ONE);
            u64 P1 = phi2(pack2(hv[i].z, hv[i].w), C3, C5, ONE);
            #pragma unroll
            for (int j = 0; j < 5; j++) {
                u64 w = svz[r][j];
                acc0[j] = fma2(w, P0, acc0[j]);
                acc1[j] = fma2(w, P1, acc1[j]);
            }
        }
    }

    // intra-block reduce over ty (4 -> 1), then one global red per (tx, j)
    if (ty > 0) {
        #pragma unroll
        for (int j = 0; j < 5; j++) {
            s_red[ty - 1][tx][j][0] = acc0[j];
            s_red[ty - 1][tx][j][1] = acc1[j];
        }
    }
    __syncthreads();
    if (ty == 0) {
        #pragma unroll
        for (int j = 0; j < 5; j++) {
            u64 a = acc0[j], b = acc1[j];
            #pragma unroll
            for (int t = 0; t < 3; t++) {
                a = add2(a, s_red[t][tx][j][0]);
                b = add2(b, s_red[t][tx][j][1]);
            }
            float a0, a1, a2, a3;
            unpack2(a, a0, a1);
            unpack2(b, a2, a3);
            float* p = g_acc + j * B_DIM + b0;
            asm volatile("red.global.add.v4.f32 [%0], {%1,%2,%3,%4};"
                         :: "l"(p), "f"(a0), "f"(a1), "f"(a2), "f"(a3) : "memory");
        }
    }
}

// ---------------------------------------------------------------------------
// Finalize: h_new[n][b] = m[n]*x_t[b] + sum_j u[n][j]*s[j][b]   (s pre-scaled)
//           y[b] = g_acc[4][b]                                  (pre-scaled)
// 128-thread blocks, grid (4, 512) = 2048 blocks, 8 rows per block.
// u[n]/m[n] fetched via warp-uniform __ldg broadcast (L1-hot) — no SMEM/sync.
// ---------------------------------------------------------------------------
#define FROWS 8
#define FIN_THREADS 128

__global__ void __launch_bounds__(FIN_THREADS, 10)
finalize_kernel(const float* __restrict__ x_t,
                const float* __restrict__ u,
                const float* __restrict__ m,
                float* __restrict__ out) {
    const int tid = threadIdx.x;
    const int n0  = blockIdx.y * FROWS;
    const int q   = blockIdx.x * FIN_THREADS + tid;   // column quad [0,512)
    const int BQ  = B_DIM / 4;

    const float4* u4 = reinterpret_cast<const float4*>(u);

    const float4 a  = __ldg(reinterpret_cast<const float4*>(g_acc) + 0 * BQ + q);
    const float4 b  = __ldg(reinterpret_cast<const float4*>(g_acc) + 1 * BQ + q);
    const float4 c  = __ldg(reinterpret_cast<const float4*>(g_acc) + 2 * BQ + q);
    const float4 d  = __ldg(reinterpret_cast<const float4*>(g_acc) + 3 * BQ + q);
    const float4 xt = __ldg(reinterpret_cast<const float4*>(x_t) + q);

    float4* op = reinterpret_cast<float4*>(out + B_DIM) + (size_t)n0 * BQ + q;

    #pragma unroll
    for (int r = 0; r < FROWS; r++) {
        const float4 uv = __ldg(u4 + n0 + r);   // warp-uniform broadcast
        const float  mm = __ldg(m + n0 + r);
        float4 o;
        o.x = fmaf(uv.x, a.x, fmaf(uv.y, b.x, fmaf(uv.z, c.x, fmaf(uv.w, d.x, mm * xt.x))));
        o.y = fmaf(uv.x, a.y, fmaf(uv.y, b.y, fmaf(uv.z, c.y, fmaf(uv.w, d.y, mm * xt.y))));
        o.z = fmaf(uv.x, a.z, fmaf(uv.y, b.z, fmaf(uv.z, c.z, fmaf(uv.w, d.z, mm * xt.z))));
        o.w = fmaf(uv.x, a.w, fmaf(uv.y, b.w, fmaf(uv.z, c.w, fmaf(uv.w, d.w, mm * xt.w))));
        *op = o;
        op += BQ;
    }

    if (blockIdx.y == 0) {   // emit y (already scaled)
        reinterpret_cast<float4*>(out)[q] =
            __ldg(reinterpret_cast<const float4*>(g_acc) + 4 * BQ + q);
    }
}

// ---------------------------------------------------------------------------
// Launch. Inputs: x_t[B], h[N*B], m[N], u[N*4], v[N*4], z[N].
// Output: [ y (B) | h_new (N*B) ] float32.
// ---------------------------------------------------------------------------
extern "C" void kernel_launch(void* const* d_in, const int* in_sizes, int n_in,
                              void* d_out, int out_size) {
    const float* x_t = (const float*)d_in[0];
    const float* h   = (const float*)d_in[1];
    const float* m   = (const float*)d_in[2];
    const float* u   = (const float*)d_in[3];
    const float* v   = (const float*)d_in[4];
    const float* z   = (const float*)d_in[5];
    float* out = (float*)d_out;
    (void)in_sizes; (void)n_in; (void)out_size;

    void* acc_ptr = nullptr;
    cudaGetSymbolAddress(&acc_ptr, g_acc);
    cudaMemsetAsync(acc_ptr, 0, 5 * B_DIM * sizeof(float));

    dim3 rgrid(B_DIM / (QUADS_PB * 4), N_DIM / BLK_ROWS);   // (8, 128) = 1024
    reduce_kernel<<<rgrid, 256>>>(h, v, z);

    dim3 fgrid(B_DIM / (4 * FIN_THREADS), N_DIM / FROWS);   // (4, 512) = 2048
    finalize_kernel<<<fgrid, FIN_THREADS>>>(x_t, u, m, out);
}